// round 13
// baseline (speedup 1.0000x reference)
#include <cuda_runtime.h>
#include <cuda_bf16.h>
#include <math.h>
#include <math_constants.h>
#include <stdint.h>

#define TOK 4096   // B*S
#define Dm  1024
#define Hh  16
#define HDim 64
#define Ff  4096
#define Ss  2048
#define NQKV 3200  // q(1024) k(1024) v(1024) router(64) pad(64)

// ---------------- fp32 scratch ----------------------------------------------
__device__ float g_qkvr[TOK*NQKV];
__device__ float g_rl [Hh*TOK*4];      // router logits, [h][tok][4] transposed
__device__ float g_x2 [TOK*Dm];
__device__ int   g_node[TOK*Hh];
__device__ float g_pos [TOK*Hh];
__device__ int   g_start [32*4];
__device__ int   g_qstart[32*Ss];
__device__ int   g_orig  [32*Ss];
__device__ float g_qp[32*Ss*HDim];
__device__ float g_kp[32*Ss*HDim];
__device__ float g_vp[32*Ss*HDim];

// ---------------- bf16 split activations ------------------------------------
__device__ __nv_bfloat16 g_hh [TOK*Dm], g_hl [TOK*Dm];
__device__ __nv_bfloat16 g_cxh[TOK*Dm], g_cxl[TOK*Dm];
__device__ __nv_bfloat16 g_s1h[TOK*Ff], g_s1l[TOK*Ff];

// ---------------- bf16 split transposed weights [N,K] -----------------------
__device__ __nv_bfloat16 g_wAh[NQKV*Dm], g_wAl[NQKV*Dm];    // Wq|Wk|Wv|Wr|0
__device__ __nv_bfloat16 g_woh[Dm*Dm],   g_wol[Dm*Dm];
__device__ __nv_bfloat16 g_w12h[2*Ff*Dm], g_w12l[2*Ff*Dm];  // w1/w2 interleaved
__device__ __nv_bfloat16 g_w3h[Dm*Ff],   g_w3l[Dm*Ff];

// ---------------- helpers -----------------------------------------------------
__device__ __forceinline__ uint32_t s2u(const void* p) {
    uint32_t a;
    asm("{ .reg .u64 t; cvta.to.shared.u64 t, %1; cvt.u32.u64 %0, t; }" : "=r"(a) : "l"(p));
    return a;
}

#define LDSM4(r, addr) \
    asm volatile("ldmatrix.sync.aligned.m8n8.x4.shared.b16 {%0,%1,%2,%3}, [%4];" \
        : "=r"((r)[0]), "=r"((r)[1]), "=r"((r)[2]), "=r"((r)[3]) : "r"(addr))

#define MMA(d, a, b) \
    asm volatile("mma.sync.aligned.m16n8k16.row.col.f32.bf16.bf16.f32 " \
        "{%0,%1,%2,%3}, {%4,%5,%6,%7}, {%8,%9}, {%0,%1,%2,%3};" \
        : "+f"((d)[0]), "+f"((d)[1]), "+f"((d)[2]), "+f"((d)[3]) \
        : "r"((a)[0]), "r"((a)[1]), "r"((a)[2]), "r"((a)[3]), "r"((b)[0]), "r"((b)[1]))

#define CPASYNC(dst, src) \
    asm volatile("cp.async.cg.shared.global [%0], [%1], 16;" :: "r"(dst), "l"(src))

// packed fp32x2 ops (Blackwell)
#define FMA2(d, a, b) \
    asm("fma.rn.f32x2 %0, %1, %2, %0;" : "+l"(d) : "l"(a), "l"(b))
#define ADD2(d, a, b) \
    asm("add.rn.f32x2 %0, %1, %2;" : "=l"(d) : "l"(a), "l"(b))
#define UNPK2(lo, hi, v) \
    asm("mov.b64 {%0, %1}, %2;" : "=f"(lo), "=f"(hi) : "l"(v))
#define BCAST2(d, s) \
    asm("mov.b64 %0, {%1, %1};" : "=l"(d) : "f"(s))

// ---------------- fast exp (FMA pipe only) ----------------------------------
__device__ __forceinline__ float fexp(float x) {
    x = fminf(fmaxf(x, -87.0f), 88.0f);
    float y = x * 1.4426950408889634f;
    float n = rintf(y);
    float f = y - n;
    float p = 1.3333558146e-3f;
    p = fmaf(p, f, 9.6181291076e-3f);
    p = fmaf(p, f, 5.5504108665e-2f);
    p = fmaf(p, f, 2.4022650696e-1f);
    p = fmaf(p, f, 6.9314718056e-1f);
    p = fmaf(p, f, 1.0f);
    return p * __int_as_float(((int)n + 127) << 23);
}

// ---------------- HMMA split-bf16 GEMM, 2-stage, 2 CTAs/SM -------------------
#define BUF_BYTES 40960
#define GH_SMEM   (2 * BUF_BYTES)

__global__ __launch_bounds__(256, 2)
void gemm_hmma(const __nv_bfloat16* __restrict__ Ah, const __nv_bfloat16* __restrict__ Al,
               const __nv_bfloat16* __restrict__ Bh, const __nv_bfloat16* __restrict__ Bl,
               const float* __restrict__ R, float* __restrict__ C,
               int M, int Nc, int ldc, int K,
               __nv_bfloat16* __restrict__ Oh, __nv_bfloat16* __restrict__ Ol, int swiglu,
               float* __restrict__ RLt) {
    extern __shared__ char smraw[];
    const int tid  = threadIdx.x;
    const int lane = tid & 31, wid = tid >> 5;
    const int m0 = blockIdx.y * 128, n0 = blockIdx.x * 128;
    const int warp_m = (wid >> 2) * 64, warp_n = (wid & 3) * 32;
    const int nc = K >> 5;
    const uint32_t sb = s2u(smraw);

    const char* gA  = (const char*)Ah + (size_t)m0 * K * 2;
    const char* gAl = (const char*)Al + (size_t)m0 * K * 2;
    const char* gB  = (const char*)Bh + (size_t)n0 * K * 2;
    const char* gBl = (const char*)Bl + (size_t)n0 * K * 2;

    int lr0 = tid >> 2,          lc0 = (tid & 3) * 16;
    int lr1 = (tid + 256) >> 2,  lc1 = lc0;

    #define ISSUE(buf, kc) do { \
        uint32_t db = sb + (buf) * BUF_BYTES; \
        size_t ko = (size_t)(kc) * 64; \
        uint32_t so0 = lr0 * 80 + lc0, so1 = lr1 * 80 + lc1; \
        size_t go0 = (size_t)lr0 * (K * 2) + ko + lc0; \
        size_t go1 = (size_t)lr1 * (K * 2) + ko + lc1; \
        CPASYNC(db + so0,         gA  + go0); CPASYNC(db + so1,         gA  + go1); \
        CPASYNC(db + 10240 + so0, gAl + go0); CPASYNC(db + 10240 + so1, gAl + go1); \
        CPASYNC(db + 20480 + so0, gB  + go0); CPASYNC(db + 20480 + so1, gB  + go1); \
        CPASYNC(db + 30720 + so0, gBl + go0); CPASYNC(db + 30720 + so1, gBl + go1); \
        asm volatile("cp.async.commit_group;"); \
    } while (0)

    ISSUE(0, 0);
    ISSUE(1, 1);

    float acc[4][4][4];
    #pragma unroll
    for (int i = 0; i < 4; i++)
        #pragma unroll
        for (int j = 0; j < 4; j++)
            #pragma unroll
            for (int q = 0; q < 4; q++) acc[i][j][q] = 0.f;

    const int a_row = (lane & 7) + ((lane >> 3) & 1) * 8;
    const int a_cb  = (lane >> 4) * 16;
    const int b_row = (lane & 7) + (lane >> 4) * 8;
    const int b_cb  = ((lane >> 3) & 1) * 16;
    const uint32_t aoff = (warp_m + a_row) * 80 + a_cb;
    const uint32_t boff = 20480 + (warp_n + b_row) * 80 + b_cb;

    #pragma unroll 1
    for (int kc = 0; kc < nc; kc++) {
        if (kc + 1 < nc) asm volatile("cp.async.wait_group 1;");
        else             asm volatile("cp.async.wait_group 0;");
        __syncthreads();
        uint32_t db = sb + (kc & 1) * BUF_BYTES;
        #pragma unroll
        for (int ks = 0; ks < 2; ks++) {
            uint32_t ah[4][4], bh[4][2], bl[4][2];
            #pragma unroll
            for (int mt = 0; mt < 4; mt++)
                LDSM4(ah[mt], db + aoff + mt * (16 * 80) + ks * 32);
            #pragma unroll
            for (int p = 0; p < 2; p++) {
                uint32_t bd = db + boff + p * (16 * 80) + ks * 32;
                LDSM4(&bh[2 * p][0], bd);
                LDSM4(&bl[2 * p][0], bd + 10240);
            }
            #pragma unroll
            for (int mt = 0; mt < 4; mt++)
                #pragma unroll
                for (int nt = 0; nt < 4; nt++) MMA(acc[mt][nt], ah[mt], bh[nt]);
            #pragma unroll
            for (int mt = 0; mt < 4; mt++)
                #pragma unroll
                for (int nt = 0; nt < 4; nt++) MMA(acc[mt][nt], ah[mt], bl[nt]);
            uint32_t al[4][4];
            #pragma unroll
            for (int mt = 0; mt < 4; mt++)
                LDSM4(al[mt], db + aoff + mt * (16 * 80) + ks * 32 + 10240);
            #pragma unroll
            for (int mt = 0; mt < 4; mt++)
                #pragma unroll
                for (int nt = 0; nt < 4; nt++) MMA(acc[mt][nt], al[mt], bh[nt]);
        }
        __syncthreads();
        if (kc + 2 < nc) ISSUE(kc & 1, kc + 2);
    }
    #undef ISSUE

    const int g  = lane >> 2;
    const int cc = (lane & 3) * 2;

    if (swiglu) {
        float* sm2 = (float*)smraw;          // [128][68] fp32 staging for a2
        if ((wid & 3) >= 2) {
            #pragma unroll
            for (int mt = 0; mt < 4; mt++) {
                int row0 = warp_m + mt * 16 + g;
                #pragma unroll
                for (int nt = 0; nt < 4; nt++) {
                    int c = warp_n - 64 + nt * 8 + cc;
                    sm2[row0 * 68 + c]           = acc[mt][nt][0];
                    sm2[row0 * 68 + c + 1]       = acc[mt][nt][1];
                    sm2[(row0 + 8) * 68 + c]     = acc[mt][nt][2];
                    sm2[(row0 + 8) * 68 + c + 1] = acc[mt][nt][3];
                }
            }
        }
        __syncthreads();
        if ((wid & 3) < 2) {
            size_t colbase = (size_t)blockIdx.x * 64;
            #pragma unroll
            for (int mt = 0; mt < 4; mt++) {
                #pragma unroll
                for (int rr = 0; rr < 2; rr++) {
                    int row = warp_m + mt * 16 + g + rr * 8;
                    size_t orow = (size_t)(m0 + row) * Ff + colbase;
                    #pragma unroll
                    for (int nt = 0; nt < 4; nt++) {
                        int c = warp_n + nt * 8 + cc;
                        float a1a = acc[mt][nt][rr * 2], a1b = acc[mt][nt][rr * 2 + 1];
                        float a2a = sm2[row * 68 + c], a2b = sm2[row * 68 + c + 1];
                        float r0 = a1a / (1.f + fexp(-a1a)) * a2a;
                        float r1 = a1b / (1.f + fexp(-a1b)) * a2b;
                        __nv_bfloat16 h0 = __float2bfloat16(r0), h1 = __float2bfloat16(r1);
                        __nv_bfloat162 H; H.x = h0; H.y = h1;
                        *(__nv_bfloat162*)(Oh + orow + c) = H;
                        __nv_bfloat162 L;
                        L.x = __float2bfloat16(r0 - __bfloat162float(h0));
                        L.y = __float2bfloat16(r1 - __bfloat162float(h1));
                        *(__nv_bfloat162*)(Ol + orow + c) = L;
                    }
                }
            }
        }
        return;
    }

    #pragma unroll
    for (int mt = 0; mt < 4; mt++) {
        int row0 = m0 + warp_m + mt * 16 + g;
        #pragma unroll
        for (int nt = 0; nt < 4; nt++) {
            int col = n0 + warp_n + nt * 8 + cc;
            if (col < Nc) {
                float2 v0 = make_float2(acc[mt][nt][0], acc[mt][nt][1]);
                float2 v1 = make_float2(acc[mt][nt][2], acc[mt][nt][3]);
                if (R) {
                    float2 r0 = *(const float2*)(R + (size_t)row0 * ldc + col);
                    float2 r1 = *(const float2*)(R + (size_t)(row0 + 8) * ldc + col);
                    v0.x += r0.x; v0.y += r0.y; v1.x += r1.x; v1.y += r1.y;
                }
                if (RLt && col >= 3072) {
                    if (col < 3136) {       // router logits -> [h][tok][4]; pad dropped
                        int c4 = col - 3072;
                        size_t o = ((size_t)(c4 >> 2) * TOK) * 4 + (c4 & 3);
                        *(float2*)(RLt + o + (size_t)row0 * 4)       = v0;
                        *(float2*)(RLt + o + (size_t)(row0 + 8) * 4) = v1;
                    }
                } else {
                    *(float2*)(C + (size_t)row0 * ldc + col)       = v0;
                    *(float2*)(C + (size_t)(row0 + 8) * ldc + col) = v1;
                }
            }
        }
    }
}

// ---------------- consolidated weight transpose + bf16 split -----------------
__global__ void wsplit_all(const float* __restrict__ Wq, const float* __restrict__ Wk,
                           const float* __restrict__ Wv, const float* __restrict__ Wo,
                           const float* __restrict__ Wr, const float* __restrict__ w1,
                           const float* __restrict__ w2, const float* __restrict__ w3,
                           __nv_bfloat16* __restrict__ wAh, __nv_bfloat16* __restrict__ wAl,
                           __nv_bfloat16* __restrict__ woh, __nv_bfloat16* __restrict__ wol,
                           __nv_bfloat16* __restrict__ w12h, __nv_bfloat16* __restrict__ w12l,
                           __nv_bfloat16* __restrict__ w3h, __nv_bfloat16* __restrict__ w3l) {
    int idx = blockIdx.x;
    const float* W;
    __nv_bfloat16 *Th, *Tl;
    int Kd, Nd, mode, Nvalid, bx, by;
    if (idx < 4096) {
        int which = idx >> 10, local = idx & 1023;
        bx = local & 31; by = local >> 5;
        Kd = Dm; Nd = Dm; mode = 0; Nvalid = Dm;
        if      (which == 0) { W = Wq; Th = wAh;             Tl = wAl; }
        else if (which == 1) { W = Wk; Th = wAh + 1024*Dm;   Tl = wAl + 1024*Dm; }
        else if (which == 2) { W = Wv; Th = wAh + 2048*Dm;   Tl = wAl + 2048*Dm; }
        else                 { W = Wo; Th = woh;             Tl = wol; }
    } else if (idx < 4224) {
        int local = idx - 4096;
        bx = local & 3; by = local >> 2;
        W = Wr; Th = wAh + (size_t)3072*Dm; Tl = wAl + (size_t)3072*Dm;
        Kd = Dm; Nd = 64; mode = 0; Nvalid = 64;
    } else if (idx < 8320) {
        int local = idx - 4224;
        bx = local & 127; by = local >> 7;
        W = w1; Th = w12h; Tl = w12l; Kd = Dm; Nd = Ff; mode = 1; Nvalid = Ff;
    } else if (idx < 12416) {
        int local = idx - 8320;
        bx = local & 127; by = local >> 7;
        W = w2; Th = w12h; Tl = w12l; Kd = Dm; Nd = Ff; mode = 2; Nvalid = Ff;
    } else {
        int local = idx - 12416;
        bx = local & 31; by = local >> 5;
        W = w3; Th = w3h; Tl = w3l; Kd = Ff; Nd = Dm; mode = 0; Nvalid = Dm;
    }

    __shared__ float t[32][33];
    int n0 = bx * 32, k0 = by * 32;
    int tx = threadIdx.x, ty = threadIdx.y;
    #pragma unroll
    for (int i = 0; i < 4; i++)
        t[ty + i * 8][tx] = (n0 + tx < Nvalid)
            ? W[(size_t)(k0 + ty + i * 8) * Nd + n0 + tx] : 0.f;
    __syncthreads();
    #pragma unroll
    for (int i = 0; i < 4; i++) {
        int r = ty + i * 8;
        int n = n0 + r;
        size_t orow = (mode == 0) ? (size_t)n
                    : (size_t)((n >> 6) * 128 + (n & 63) + ((mode == 2) ? 64 : 0));
        float v = t[tx][r];
        __nv_bfloat16 hb = __float2bfloat16(v);
        size_t o = orow * Kd + k0 + tx;
        Th[o] = hb;
        Tl[o] = __float2bfloat16(v - __bfloat162float(hb));
    }
}

// ---------------- rmsnorm -> bf16 split --------------------------------------
__global__ void rmsnorm_k(const float* __restrict__ x, const float* __restrict__ w,
                          __nv_bfloat16* __restrict__ oh, __nv_bfloat16* __restrict__ ol) {
    int row = blockIdx.x;
    const float4* xr = (const float4*)(x + (size_t)row * Dm);
    float4 v = xr[threadIdx.x];
    float ss = v.x*v.x + v.y*v.y + v.z*v.z + v.w*v.w;
    #pragma unroll
    for (int o = 16; o; o >>= 1) ss += __shfl_xor_sync(0xffffffffu, ss, o);
    __shared__ float sws[8];
    int lane = threadIdx.x & 31, wid = threadIdx.x >> 5;
    if (lane == 0) sws[wid] = ss;
    __syncthreads();
    if (threadIdx.x == 0) {
        float t = 0.f;
        #pragma unroll
        for (int i = 0; i < 8; i++) t += sws[i];
        sws[0] = rsqrtf(t * (1.0f / Dm) + 1e-6f);
    }
    __syncthreads();
    float inv = sws[0];
    float4 wv = ((const float4*)w)[threadIdx.x];
    float4 o4;
    o4.x = v.x * inv * wv.x; o4.y = v.y * inv * wv.y;
    o4.z = v.z * inv * wv.z; o4.w = v.w * inv * wv.w;
    __nv_bfloat16 h0 = __float2bfloat16(o4.x), h1 = __float2bfloat16(o4.y);
    __nv_bfloat16 h2 = __float2bfloat16(o4.z), h3 = __float2bfloat16(o4.w);
    __nv_bfloat162 H0; H0.x = h0; H0.y = h1;
    __nv_bfloat162 H1; H1.x = h2; H1.y = h3;
    __nv_bfloat162* ph = (__nv_bfloat162*)(oh + (size_t)row * Dm);
    ph[threadIdx.x * 2]     = H0;
    ph[threadIdx.x * 2 + 1] = H1;
    __nv_bfloat162 L0, L1;
    L0.x = __float2bfloat16(o4.x - __bfloat162float(h0));
    L0.y = __float2bfloat16(o4.y - __bfloat162float(h1));
    L1.x = __float2bfloat16(o4.z - __bfloat162float(h2));
    L1.y = __float2bfloat16(o4.w - __bfloat162float(h3));
    __nv_bfloat162* pl = (__nv_bfloat162*)(ol + (size_t)row * Dm);
    pl[threadIdx.x * 2]     = L0;
    pl[threadIdx.x * 2 + 1] = L1;
}

// ---------------- node/pos + partition starts (parallel scan) ----------------
__global__ void node_pos_k() {
    int bh = blockIdx.x;
    int b = bh >> 4, h = bh & 15;
    int t = threadIdx.x;
    int lane = t & 31, wid = t >> 5;
    __shared__ int cnts[256][4];
    __shared__ int base[256][4];
    __shared__ int tot[4];
    int myn[8], posl[8];
    int local[4] = {0, 0, 0, 0};
    #pragma unroll
    for (int j = 0; j < 8; j++) {
        int s = t * 8 + j;
        int tok = b * Ss + s;
        const float* lp = g_rl + ((size_t)h * TOK + tok) * 4;   // coalesced layout
        float l0 = lp[0], l1 = lp[1], l2 = lp[2], l3 = lp[3];
        int n = 0; float bv = l0;
        if (l1 > bv) { bv = l1; n = 1; }
        if (l2 > bv) { bv = l2; n = 2; }
        if (l3 > bv) { bv = l3; n = 3; }
        myn[j] = n;
        posl[j] = local[n];
        local[n]++;
    }
    cnts[t][0] = local[0]; cnts[t][1] = local[1];
    cnts[t][2] = local[2]; cnts[t][3] = local[3];
    __syncthreads();
    if (wid < 4) {
        int v = wid;
        int vals[8], part = 0;
        #pragma unroll
        for (int m = 0; m < 8; m++) { vals[m] = cnts[lane * 8 + m][v]; part += vals[m]; }
        int scan = part;
        #pragma unroll
        for (int o = 1; o < 32; o <<= 1) {
            int u = __shfl_up_sync(0xffffffffu, scan, o);
            if (lane >= o) scan += u;
        }
        int excl = scan - part;
        int run = 0;
        #pragma unroll
        for (int m = 0; m < 8; m++) { base[lane * 8 + m][v] = excl + run; run += vals[m]; }
        if (lane == 31) tot[v] = excl + part;
    }
    __syncthreads();
    if (t == 0) {
        int st = 0;
        #pragma unroll
        for (int v = 0; v < 4; v++) { g_start[bh * 4 + v] = st; st += tot[v]; }
    }
    __syncthreads();
    #pragma unroll
    for (int j = 0; j < 8; j++) {
        int s = t * 8 + j;
        int tok = b * Ss + s;
        int n = myn[j];
        g_node[tok * Hh + h] = n;
        g_pos[tok * Hh + h] = (float)(base[t][n] + posl[j]);
    }
}

// ---------------- permute (node partition) + RoPE ----------------------------
__global__ void permute_k() {
    int inst = blockIdx.x * 8 + (threadIdx.x >> 5);   // tok*16 + h
    int lane = threadIdx.x & 31;
    int tok = inst >> 4, h = inst & 15;
    int b = tok >> 11;
    int bh = b * 16 + h;
    int n = g_node[tok * Hh + h];
    float pos = g_pos[tok * Hh + h];
    int startn = g_start[bh * 4 + n];
    int slot = startn + (int)pos;
    const float* src = g_qkvr + (size_t)tok * NQKV;
    float invf = exp2f(-(float)lane * (13.287712379549449f / 32.0f));
    float ang = pos * invf;
    float s, c;
    sincosf(ang, &s, &c);
    size_t drow = ((size_t)bh * Ss + slot) * HDim;
    float q1 = src[h * 64 + lane], q2 = src[h * 64 + lane + 32];
    g_qp[drow + lane]      = q1 * c - q2 * s;
    g_qp[drow + lane + 32] = q2 * c + q1 * s;
    float k1 = src[1024 + h * 64 + lane], k2 = src[1024 + h * 64 + lane + 32];
    g_kp[drow + lane]      = k1 * c - k2 * s;
    g_kp[drow + lane + 32] = k2 * c + k1 * s;
    g_vp[drow + lane]      = src[2048 + h * 64 + lane];
    g_vp[drow + lane + 32] = src[2048 + h * 64 + lane + 32];
    if (lane == 0) {
        g_qstart[bh * Ss + slot] = startn;
        g_orig  [bh * Ss + slot] = tok;
    }
}

// ---------------- attention: maxless partitioned flash, packed f32x2 ---------
#define ATTN_SMEM ((4096 + 4096) * 4)
__global__ __launch_bounds__(128)
void attn_k() {
    int bh = blockIdx.y;
    int h = bh & 15;
    int q0 = blockIdx.x * 128;
    int tid = threadIdx.x;
    int j = q0 + tid;
    size_t base = (size_t)bh * Ss;
    extern __shared__ float sm[];
    float* Ks = sm;
    float* Vs = sm + 4096;

    unsigned long long q2[32], acc2[32];
    {
        const ulonglong2* qp = (const ulonglong2*)(g_qp + (base + j) * HDim);
        #pragma unroll
        for (int i = 0; i < 16; i++) {
            ulonglong2 t = qp[i];
            q2[2 * i] = t.x; q2[2 * i + 1] = t.y;
        }
    }
    #pragma unroll
    for (int d = 0; d < 32; d++) acc2[d] = 0ULL;

    int startq = g_qstart[base + j];
    int orig   = g_orig[base + j];
    int kt0 = g_qstart[base + q0] >> 6;
    int ktE = (q0 >> 6) + 2;

    float l = 0.f;

    for (int kt = kt0; kt < ktE; ++kt) {
        int kb = kt * 64;
        __syncthreads();
        for (int e = tid; e < 1024; e += 128) {
            int r = e >> 4, c = (e & 15) * 4;
            size_t srow = (base + kb + r) * HDim;
            *(float4*)&Ks[r * 64 + c] = *(const float4*)(g_kp + srow + c);
            *(float4*)&Vs[r * 64 + c] = *(const float4*)(g_vp + srow + c);
        }
        __syncthreads();

        int kk0 = startq - kb; kk0 = kk0 > 0 ? kk0 : 0;
        int kk1 = j - kb + 1;  kk1 = kk1 < 64 ? kk1 : 64;

        #pragma unroll 1
        for (int kk = kk0; kk < kk1; ++kk) {
            const ulonglong2* kr = (const ulonglong2*)&Ks[kk * 64];
            unsigned long long sA = 0ULL, sB = 0ULL, sC = 0ULL, sD = 0ULL;
            #pragma unroll
            for (int i = 0; i < 8; i++) {
                ulonglong2 k0 = kr[2 * i], k1 = kr[2 * i + 1];
                FMA2(sA, q2[4 * i + 0], k0.x);
                FMA2(sB, q2[4 * i + 1], k0.y);
                FMA2(sC, q2[4 * i + 2], k1.x);
                FMA2(sD, q2[4 * i + 3], k1.y);
            }
            ADD2(sA, sA, sB);
            ADD2(sC, sC, sD);
            ADD2(sA, sA, sC);
            float slo, shi;
            UNPK2(slo, shi, sA);
            float p = fexp((slo + shi) * 0.125f);
            l += p;
            unsigned long long pp;
            BCAST2(pp, p);
            const ulonglong2* vr = (const ulonglong2*)&Vs[kk * 64];
            #pragma unroll
            for (int i = 0; i < 16; i++) {
                ulonglong2 vv = vr[i];
                FMA2(acc2[2 * i],     pp, vv.x);
                FMA2(acc2[2 * i + 1], pp, vv.y);
            }
        }
    }
    float inv = 1.f / l;
    __nv_bfloat162* oh = (__nv_bfloat162*)(g_cxh + (size_t)orig * Dm + h * HDim);
    __nv_bfloat162* ol = (__nv_bfloat162*)(g_cxl + (size_t)orig * Dm + h * HDim);
    #pragma unroll
    for (int d2 = 0; d2 < 32; d2++) {
        float a0, a1;
        UNPK2(a0, a1, acc2[d2]);
        float v0 = a0 * inv, v1 = a1 * inv;
        __nv_bfloat16 h0 = __float2bfloat16(v0), h1 = __float2bfloat16(v1);
        __nv_bfloat162 H; H.x = h0; H.y = h1;
        oh[d2] = H;
        __nv_bfloat162 L;
        L.x = __float2bfloat16(v0 - __bfloat162float(h0));
        L.y = __float2bfloat16(v1 - __bfloat162float(h1));
        ol[d2] = L;
    }
}

// ---------------- host launcher ----------------------------------------------
#define SYM(p, s) do { void* _t; cudaGetSymbolAddress(&_t, s); p = (decltype(p))_t; } while (0)

extern "C" void kernel_launch(void* const* d_in, const int* in_sizes, int n_in,
                              void* d_out, int out_size) {
    const float* x      = (const float*)d_in[0];
    const float* attn_w = (const float*)d_in[1];
    const float* ffn_w  = (const float*)d_in[2];
    const float* Wq     = (const float*)d_in[3];
    const float* Wk     = (const float*)d_in[4];
    const float* Wv     = (const float*)d_in[5];
    const float* Wo     = (const float*)d_in[6];
    const float* Wr     = (const float*)d_in[7];
    const float* w1     = (const float*)d_in[8];
    const float* w2     = (const float*)d_in[9];
    const float* w3     = (const float*)d_in[10];
    float* out = (float*)d_out;

    float *p_qkvr, *p_x2, *p_rl;
    SYM(p_qkvr, g_qkvr); SYM(p_x2, g_x2); SYM(p_rl, g_rl);
    __nv_bfloat16 *p_hh, *p_hl, *p_cxh, *p_cxl, *p_s1h, *p_s1l;
    SYM(p_hh, g_hh); SYM(p_hl, g_hl); SYM(p_cxh, g_cxh); SYM(p_cxl, g_cxl);
    SYM(p_s1h, g_s1h); SYM(p_s1l, g_s1l);
    __nv_bfloat16 *wAh, *wAl, *woh, *wol, *w12h, *w12l, *w3h, *w3l;
    SYM(wAh, g_wAh); SYM(wAl, g_wAl); SYM(woh, g_woh); SYM(wol, g_wol);
    SYM(w12h, g_w12h); SYM(w12l, g_w12l); SYM(w3h, g_w3h); SYM(w3l, g_w3l);

    cudaFuncSetAttribute(attn_k, cudaFuncAttributeMaxDynamicSharedMemorySize, ATTN_SMEM);
    cudaFuncSetAttribute(gemm_hmma, cudaFuncAttributeMaxDynamicSharedMemorySize, GH_SMEM);

    // single consolidated weight-prep launch
    wsplit_all<<<16512, dim3(32, 8)>>>(Wq, Wk, Wv, Wo, Wr, w1, w2, w3,
                                       wAh, wAl, woh, wol, w12h, w12l, w3h, w3l);

    // h = rmsnorm(x) -> bf16 split
    rmsnorm_k<<<TOK, 256>>>(x, attn_w, p_hh, p_hl);

    // fused q|k|v|router GEMM (router logits -> compact transposed g_rl)
    gemm_hmma<<<dim3(NQKV/128, TOK/128), 256, GH_SMEM>>>(
        p_hh, p_hl, wAh, wAl, nullptr, p_qkvr, TOK, NQKV, NQKV, Dm,
        nullptr, nullptr, 0, p_rl);

    // node/pos + partition & rope ; attention
    node_pos_k<<<32, 256>>>();
    permute_k<<<TOK * Hh / 8, 256>>>();
    attn_k<<<dim3(Ss / 128, 2 * Hh), 128, ATTN_SMEM>>>();

    // x2 = x + ctx @ Wo
    gemm_hmma<<<dim3(Dm/128, TOK/128), 256, GH_SMEM>>>(
        p_cxh, p_cxl, woh, wol, x, p_x2, TOK, Dm, Dm, Dm, nullptr, nullptr, 0, nullptr);

    // h2 = rmsnorm(x2)
    rmsnorm_k<<<TOK, 256>>>(p_x2, ffn_w, p_hh, p_hl);

    // fused w1|w2 GEMM with SwiGLU epilogue -> s1 (bf16 split)
    gemm_hmma<<<dim3(2*Ff/128, TOK/128), 256, GH_SMEM>>>(
        p_hh, p_hl, w12h, w12l, nullptr, nullptr, TOK, 2*Ff, 0, Dm,
        p_s1h, p_s1l, 1, nullptr);

    // out = x2 + s1 @ w3
    gemm_hmma<<<dim3(Dm/128, TOK/128), 256, GH_SMEM>>>(
        p_s1h, p_s1l, w3h, w3l, p_x2, out, TOK, Dm, Dm, Ff, nullptr, nullptr, 0, nullptr);
}

// round 14
// speedup vs baseline: 1.0341x; 1.0341x over previous
#include <cuda_runtime.h>
#include <cuda_bf16.h>
#include <math.h>
#include <math_constants.h>
#include <stdint.h>

#define TOK 4096   // B*S
#define Dm  1024
#define Hh  16
#define HDim 64
#define Ff  4096
#define Ss  2048
#define NQKV 3200  // q(1024) k(1024) v(1024) router(64) pad(64)

// ---------------- fp32 scratch ----------------------------------------------
__device__ float g_qkvr[TOK*NQKV];
__device__ float g_x2 [TOK*Dm];
__device__ int   g_node[TOK*Hh];
__device__ float g_pos [TOK*Hh];
__device__ int   g_start [32*4];
__device__ int   g_qstart[32*Ss];
__device__ int   g_orig  [32*Ss];
__device__ float g_qp[32*Ss*HDim];
__device__ float g_kp[32*Ss*HDim];
__device__ float g_vp[32*Ss*HDim];

// ---------------- bf16 split activations ------------------------------------
__device__ __nv_bfloat16 g_hh [TOK*Dm], g_hl [TOK*Dm];
__device__ __nv_bfloat16 g_cxh[TOK*Dm], g_cxl[TOK*Dm];
__device__ __nv_bfloat16 g_s1h[TOK*Ff], g_s1l[TOK*Ff];

// ---------------- bf16 split transposed weights [N,K] -----------------------
__device__ __nv_bfloat16 g_wAh[NQKV*Dm], g_wAl[NQKV*Dm];    // Wq|Wk|Wv|Wr|0
__device__ __nv_bfloat16 g_woh[Dm*Dm],   g_wol[Dm*Dm];
__device__ __nv_bfloat16 g_w12h[2*Ff*Dm], g_w12l[2*Ff*Dm];  // w1/w2 interleaved
__device__ __nv_bfloat16 g_w3h[Dm*Ff],   g_w3l[Dm*Ff];

// ---------------- helpers -----------------------------------------------------
__device__ __forceinline__ uint32_t s2u(const void* p) {
    uint32_t a;
    asm("{ .reg .u64 t; cvta.to.shared.u64 t, %1; cvt.u32.u64 %0, t; }" : "=r"(a) : "l"(p));
    return a;
}

#define LDSM4(r, addr) \
    asm volatile("ldmatrix.sync.aligned.m8n8.x4.shared.b16 {%0,%1,%2,%3}, [%4];" \
        : "=r"((r)[0]), "=r"((r)[1]), "=r"((r)[2]), "=r"((r)[3]) : "r"(addr))

#define MMA(d, a, b) \
    asm volatile("mma.sync.aligned.m16n8k16.row.col.f32.bf16.bf16.f32 " \
        "{%0,%1,%2,%3}, {%4,%5,%6,%7}, {%8,%9}, {%0,%1,%2,%3};" \
        : "+f"((d)[0]), "+f"((d)[1]), "+f"((d)[2]), "+f"((d)[3]) \
        : "r"((a)[0]), "r"((a)[1]), "r"((a)[2]), "r"((a)[3]), "r"((b)[0]), "r"((b)[1]))

#define CPASYNC(dst, src) \
    asm volatile("cp.async.cg.shared.global [%0], [%1], 16;" :: "r"(dst), "l"(src))

// ---------------- fast exp (FMA pipe only) ----------------------------------
__device__ __forceinline__ float fexp(float x) {
    x = fminf(fmaxf(x, -87.0f), 88.0f);
    float y = x * 1.4426950408889634f;
    float n = rintf(y);
    float f = y - n;
    float p = 1.3333558146e-3f;
    p = fmaf(p, f, 9.6181291076e-3f);
    p = fmaf(p, f, 5.5504108665e-2f);
    p = fmaf(p, f, 2.4022650696e-1f);
    p = fmaf(p, f, 6.9314718056e-1f);
    p = fmaf(p, f, 1.0f);
    return p * __int_as_float(((int)n + 127) << 23);
}

// ---------------- HMMA split-bf16 GEMM, 2-stage, 2 CTAs/SM -------------------
#define BUF_BYTES 40960
#define GH_SMEM   (2 * BUF_BYTES)

__global__ __launch_bounds__(256, 2)
void gemm_hmma(const __nv_bfloat16* __restrict__ Ah, const __nv_bfloat16* __restrict__ Al,
               const __nv_bfloat16* __restrict__ Bh, const __nv_bfloat16* __restrict__ Bl,
               const float* __restrict__ R, float* __restrict__ C,
               int M, int Nc, int ldc, int K,
               __nv_bfloat16* __restrict__ Oh, __nv_bfloat16* __restrict__ Ol, int swiglu) {
    extern __shared__ char smraw[];
    const int tid  = threadIdx.x;
    const int lane = tid & 31, wid = tid >> 5;
    const int m0 = blockIdx.y * 128, n0 = blockIdx.x * 128;
    const int warp_m = (wid >> 2) * 64, warp_n = (wid & 3) * 32;
    const int nc = K >> 5;
    const uint32_t sb = s2u(smraw);

    const char* gA  = (const char*)Ah + (size_t)m0 * K * 2;
    const char* gAl = (const char*)Al + (size_t)m0 * K * 2;
    const char* gB  = (const char*)Bh + (size_t)n0 * K * 2;
    const char* gBl = (const char*)Bl + (size_t)n0 * K * 2;

    int lr0 = tid >> 2,          lc0 = (tid & 3) * 16;
    int lr1 = (tid + 256) >> 2,  lc1 = lc0;

    #define ISSUE(buf, kc) do { \
        uint32_t db = sb + (buf) * BUF_BYTES; \
        size_t ko = (size_t)(kc) * 64; \
        uint32_t so0 = lr0 * 80 + lc0, so1 = lr1 * 80 + lc1; \
        size_t go0 = (size_t)lr0 * (K * 2) + ko + lc0; \
        size_t go1 = (size_t)lr1 * (K * 2) + ko + lc1; \
        CPASYNC(db + so0,         gA  + go0); CPASYNC(db + so1,         gA  + go1); \
        CPASYNC(db + 10240 + so0, gAl + go0); CPASYNC(db + 10240 + so1, gAl + go1); \
        CPASYNC(db + 20480 + so0, gB  + go0); CPASYNC(db + 20480 + so1, gB  + go1); \
        CPASYNC(db + 30720 + so0, gBl + go0); CPASYNC(db + 30720 + so1, gBl + go1); \
        asm volatile("cp.async.commit_group;"); \
    } while (0)

    ISSUE(0, 0);
    ISSUE(1, 1);

    float acc[4][4][4];
    #pragma unroll
    for (int i = 0; i < 4; i++)
        #pragma unroll
        for (int j = 0; j < 4; j++)
            #pragma unroll
            for (int q = 0; q < 4; q++) acc[i][j][q] = 0.f;

    const int a_row = (lane & 7) + ((lane >> 3) & 1) * 8;
    const int a_cb  = (lane >> 4) * 16;
    const int b_row = (lane & 7) + (lane >> 4) * 8;
    const int b_cb  = ((lane >> 3) & 1) * 16;
    const uint32_t aoff = (warp_m + a_row) * 80 + a_cb;
    const uint32_t boff = 20480 + (warp_n + b_row) * 80 + b_cb;

    #pragma unroll 1
    for (int kc = 0; kc < nc; kc++) {
        if (kc + 1 < nc) asm volatile("cp.async.wait_group 1;");
        else             asm volatile("cp.async.wait_group 0;");
        __syncthreads();
        uint32_t db = sb + (kc & 1) * BUF_BYTES;
        #pragma unroll
        for (int ks = 0; ks < 2; ks++) {
            uint32_t ah[4][4], bh[4][2], bl[4][2];
            #pragma unroll
            for (int mt = 0; mt < 4; mt++)
                LDSM4(ah[mt], db + aoff + mt * (16 * 80) + ks * 32);
            #pragma unroll
            for (int p = 0; p < 2; p++) {
                uint32_t bd = db + boff + p * (16 * 80) + ks * 32;
                LDSM4(&bh[2 * p][0], bd);
                LDSM4(&bl[2 * p][0], bd + 10240);
            }
            #pragma unroll
            for (int mt = 0; mt < 4; mt++)
                #pragma unroll
                for (int nt = 0; nt < 4; nt++) MMA(acc[mt][nt], ah[mt], bh[nt]);
            #pragma unroll
            for (int mt = 0; mt < 4; mt++)
                #pragma unroll
                for (int nt = 0; nt < 4; nt++) MMA(acc[mt][nt], ah[mt], bl[nt]);
            uint32_t al[4][4];
            #pragma unroll
            for (int mt = 0; mt < 4; mt++)
                LDSM4(al[mt], db + aoff + mt * (16 * 80) + ks * 32 + 10240);
            #pragma unroll
            for (int mt = 0; mt < 4; mt++)
                #pragma unroll
                for (int nt = 0; nt < 4; nt++) MMA(acc[mt][nt], al[mt], bh[nt]);
        }
        __syncthreads();
        if (kc + 2 < nc) ISSUE(kc & 1, kc + 2);
    }
    #undef ISSUE

    const int g  = lane >> 2;
    const int cc = (lane & 3) * 2;

    if (swiglu) {
        float* sm2 = (float*)smraw;          // [128][68] fp32 staging for a2
        if ((wid & 3) >= 2) {
            #pragma unroll
            for (int mt = 0; mt < 4; mt++) {
                int row0 = warp_m + mt * 16 + g;
                #pragma unroll
                for (int nt = 0; nt < 4; nt++) {
                    int c = warp_n - 64 + nt * 8 + cc;
                    sm2[row0 * 68 + c]           = acc[mt][nt][0];
                    sm2[row0 * 68 + c + 1]       = acc[mt][nt][1];
                    sm2[(row0 + 8) * 68 + c]     = acc[mt][nt][2];
                    sm2[(row0 + 8) * 68 + c + 1] = acc[mt][nt][3];
                }
            }
        }
        __syncthreads();
        if ((wid & 3) < 2) {
            size_t colbase = (size_t)blockIdx.x * 64;
            #pragma unroll
            for (int mt = 0; mt < 4; mt++) {
                #pragma unroll
                for (int rr = 0; rr < 2; rr++) {
                    int row = warp_m + mt * 16 + g + rr * 8;
                    size_t orow = (size_t)(m0 + row) * Ff + colbase;
                    #pragma unroll
                    for (int nt = 0; nt < 4; nt++) {
                        int c = warp_n + nt * 8 + cc;
                        float a1a = acc[mt][nt][rr * 2], a1b = acc[mt][nt][rr * 2 + 1];
                        float a2a = sm2[row * 68 + c], a2b = sm2[row * 68 + c + 1];
                        float r0 = a1a / (1.f + fexp(-a1a)) * a2a;
                        float r1 = a1b / (1.f + fexp(-a1b)) * a2b;
                        __nv_bfloat16 h0 = __float2bfloat16(r0), h1 = __float2bfloat16(r1);
                        __nv_bfloat162 H; H.x = h0; H.y = h1;
                        *(__nv_bfloat162*)(Oh + orow + c) = H;
                        __nv_bfloat162 L;
                        L.x = __float2bfloat16(r0 - __bfloat162float(h0));
                        L.y = __float2bfloat16(r1 - __bfloat162float(h1));
                        *(__nv_bfloat162*)(Ol + orow + c) = L;
                    }
                }
            }
        }
        return;
    }

    #pragma unroll
    for (int mt = 0; mt < 4; mt++) {
        int row0 = m0 + warp_m + mt * 16 + g;
        #pragma unroll
        for (int nt = 0; nt < 4; nt++) {
            int col = n0 + warp_n + nt * 8 + cc;
            if (col < Nc) {
                float2 v0 = make_float2(acc[mt][nt][0], acc[mt][nt][1]);
                float2 v1 = make_float2(acc[mt][nt][2], acc[mt][nt][3]);
                if (R) {
                    float2 r0 = *(const float2*)(R + (size_t)row0 * ldc + col);
                    float2 r1 = *(const float2*)(R + (size_t)(row0 + 8) * ldc + col);
                    v0.x += r0.x; v0.y += r0.y; v1.x += r1.x; v1.y += r1.y;
                }
                *(float2*)(C + (size_t)row0 * ldc + col)       = v0;
                *(float2*)(C + (size_t)(row0 + 8) * ldc + col) = v1;
            }
        }
    }
}

// ---------------- consolidated weight transpose + bf16 split -----------------
__global__ void wsplit_all(const float* __restrict__ Wq, const float* __restrict__ Wk,
                           const float* __restrict__ Wv, const float* __restrict__ Wo,
                           const float* __restrict__ Wr, const float* __restrict__ w1,
                           const float* __restrict__ w2, const float* __restrict__ w3,
                           __nv_bfloat16* __restrict__ wAh, __nv_bfloat16* __restrict__ wAl,
                           __nv_bfloat16* __restrict__ woh, __nv_bfloat16* __restrict__ wol,
                           __nv_bfloat16* __restrict__ w12h, __nv_bfloat16* __restrict__ w12l,
                           __nv_bfloat16* __restrict__ w3h, __nv_bfloat16* __restrict__ w3l) {
    int idx = blockIdx.x;
    const float* W;
    __nv_bfloat16 *Th, *Tl;
    int Kd, Nd, mode, Nvalid, bx, by;
    if (idx < 4096) {
        int which = idx >> 10, local = idx & 1023;
        bx = local & 31; by = local >> 5;
        Kd = Dm; Nd = Dm; mode = 0; Nvalid = Dm;
        if      (which == 0) { W = Wq; Th = wAh;             Tl = wAl; }
        else if (which == 1) { W = Wk; Th = wAh + 1024*Dm;   Tl = wAl + 1024*Dm; }
        else if (which == 2) { W = Wv; Th = wAh + 2048*Dm;   Tl = wAl + 2048*Dm; }
        else                 { W = Wo; Th = woh;             Tl = wol; }
    } else if (idx < 4224) {
        int local = idx - 4096;
        bx = local & 3; by = local >> 2;
        W = Wr; Th = wAh + (size_t)3072*Dm; Tl = wAl + (size_t)3072*Dm;
        Kd = Dm; Nd = 64; mode = 0; Nvalid = 64;
    } else if (idx < 8320) {
        int local = idx - 4224;
        bx = local & 127; by = local >> 7;
        W = w1; Th = w12h; Tl = w12l; Kd = Dm; Nd = Ff; mode = 1; Nvalid = Ff;
    } else if (idx < 12416) {
        int local = idx - 8320;
        bx = local & 127; by = local >> 7;
        W = w2; Th = w12h; Tl = w12l; Kd = Dm; Nd = Ff; mode = 2; Nvalid = Ff;
    } else {
        int local = idx - 12416;
        bx = local & 31; by = local >> 5;
        W = w3; Th = w3h; Tl = w3l; Kd = Ff; Nd = Dm; mode = 0; Nvalid = Dm;
    }

    __shared__ float t[32][33];
    int n0 = bx * 32, k0 = by * 32;
    int tx = threadIdx.x, ty = threadIdx.y;
    #pragma unroll
    for (int i = 0; i < 4; i++)
        t[ty + i * 8][tx] = (n0 + tx < Nvalid)
            ? W[(size_t)(k0 + ty + i * 8) * Nd + n0 + tx] : 0.f;
    __syncthreads();
    #pragma unroll
    for (int i = 0; i < 4; i++) {
        int r = ty + i * 8;
        int n = n0 + r;
        size_t orow = (mode == 0) ? (size_t)n
                    : (size_t)((n >> 6) * 128 + (n & 63) + ((mode == 2) ? 64 : 0));
        float v = t[tx][r];
        __nv_bfloat16 hb = __float2bfloat16(v);
        size_t o = orow * Kd + k0 + tx;
        Th[o] = hb;
        Tl[o] = __float2bfloat16(v - __bfloat162float(hb));
    }
}

// ---------------- rmsnorm -> bf16 split --------------------------------------
__global__ void rmsnorm_k(const float* __restrict__ x, const float* __restrict__ w,
                          __nv_bfloat16* __restrict__ oh, __nv_bfloat16* __restrict__ ol) {
    int row = blockIdx.x;
    const float4* xr = (const float4*)(x + (size_t)row * Dm);
    float4 v = xr[threadIdx.x];
    float ss = v.x*v.x + v.y*v.y + v.z*v.z + v.w*v.w;
    #pragma unroll
    for (int o = 16; o; o >>= 1) ss += __shfl_xor_sync(0xffffffffu, ss, o);
    __shared__ float sws[8];
    int lane = threadIdx.x & 31, wid = threadIdx.x >> 5;
    if (lane == 0) sws[wid] = ss;
    __syncthreads();
    if (threadIdx.x == 0) {
        float t = 0.f;
        #pragma unroll
        for (int i = 0; i < 8; i++) t += sws[i];
        sws[0] = rsqrtf(t * (1.0f / Dm) + 1e-6f);
    }
    __syncthreads();
    float inv = sws[0];
    float4 wv = ((const float4*)w)[threadIdx.x];
    float4 o4;
    o4.x = v.x * inv * wv.x; o4.y = v.y * inv * wv.y;
    o4.z = v.z * inv * wv.z; o4.w = v.w * inv * wv.w;
    __nv_bfloat16 h0 = __float2bfloat16(o4.x), h1 = __float2bfloat16(o4.y);
    __nv_bfloat16 h2 = __float2bfloat16(o4.z), h3 = __float2bfloat16(o4.w);
    __nv_bfloat162 H0; H0.x = h0; H0.y = h1;
    __nv_bfloat162 H1; H1.x = h2; H1.y = h3;
    __nv_bfloat162* ph = (__nv_bfloat162*)(oh + (size_t)row * Dm);
    ph[threadIdx.x * 2]     = H0;
    ph[threadIdx.x * 2 + 1] = H1;
    __nv_bfloat162 L0, L1;
    L0.x = __float2bfloat16(o4.x - __bfloat162float(h0));
    L0.y = __float2bfloat16(o4.y - __bfloat162float(h1));
    L1.x = __float2bfloat16(o4.z - __bfloat162float(h2));
    L1.y = __float2bfloat16(o4.w - __bfloat162float(h3));
    __nv_bfloat162* pl = (__nv_bfloat162*)(ol + (size_t)row * Dm);
    pl[threadIdx.x * 2]     = L0;
    pl[threadIdx.x * 2 + 1] = L1;
}

// ---------------- node/pos + partition starts (parallel scan) ----------------
__global__ void node_pos_k() {
    int bh = blockIdx.x;
    int b = bh >> 4, h = bh & 15;
    int t = threadIdx.x;
    int lane = t & 31, wid = t >> 5;
    __shared__ int cnts[256][4];
    __shared__ int base[256][4];
    __shared__ int tot[4];
    int myn[8], posl[8];
    int local[4] = {0, 0, 0, 0};
    #pragma unroll
    for (int j = 0; j < 8; j++) {
        int s = t * 8 + j;
        int tok = b * Ss + s;
        const float* lp = g_qkvr + (size_t)tok * NQKV + 3072 + h * 4;
        float l0 = lp[0], l1 = lp[1], l2 = lp[2], l3 = lp[3];
        int n = 0; float bv = l0;
        if (l1 > bv) { bv = l1; n = 1; }
        if (l2 > bv) { bv = l2; n = 2; }
        if (l3 > bv) { bv = l3; n = 3; }
        myn[j] = n;
        posl[j] = local[n];
        local[n]++;
    }
    cnts[t][0] = local[0]; cnts[t][1] = local[1];
    cnts[t][2] = local[2]; cnts[t][3] = local[3];
    __syncthreads();
    if (wid < 4) {
        int v = wid;
        int vals[8], part = 0;
        #pragma unroll
        for (int m = 0; m < 8; m++) { vals[m] = cnts[lane * 8 + m][v]; part += vals[m]; }
        int scan = part;
        #pragma unroll
        for (int o = 1; o < 32; o <<= 1) {
            int u = __shfl_up_sync(0xffffffffu, scan, o);
            if (lane >= o) scan += u;
        }
        int excl = scan - part;
        int run = 0;
        #pragma unroll
        for (int m = 0; m < 8; m++) { base[lane * 8 + m][v] = excl + run; run += vals[m]; }
        if (lane == 31) tot[v] = excl + part;
    }
    __syncthreads();
    if (t == 0) {
        int st = 0;
        #pragma unroll
        for (int v = 0; v < 4; v++) { g_start[bh * 4 + v] = st; st += tot[v]; }
    }
    __syncthreads();
    #pragma unroll
    for (int j = 0; j < 8; j++) {
        int s = t * 8 + j;
        int tok = b * Ss + s;
        int n = myn[j];
        g_node[tok * Hh + h] = n;
        g_pos[tok * Hh + h] = (float)(base[t][n] + posl[j]);
    }
}

// ---------------- permute (node partition) + RoPE ----------------------------
__global__ void permute_k() {
    int inst = blockIdx.x * 8 + (threadIdx.x >> 5);   // tok*16 + h
    int lane = threadIdx.x & 31;
    int tok = inst >> 4, h = inst & 15;
    int b = tok >> 11;
    int bh = b * 16 + h;
    int n = g_node[tok * Hh + h];
    float pos = g_pos[tok * Hh + h];
    int startn = g_start[bh * 4 + n];
    int slot = startn + (int)pos;
    const float* src = g_qkvr + (size_t)tok * NQKV;
    float invf = exp2f(-(float)lane * (13.287712379549449f / 32.0f));
    float ang = pos * invf;
    float s, c;
    sincosf(ang, &s, &c);
    size_t drow = ((size_t)bh * Ss + slot) * HDim;
    float q1 = src[h * 64 + lane], q2 = src[h * 64 + lane + 32];
    g_qp[drow + lane]      = q1 * c - q2 * s;
    g_qp[drow + lane + 32] = q2 * c + q1 * s;
    float k1 = src[1024 + h * 64 + lane], k2 = src[1024 + h * 64 + lane + 32];
    g_kp[drow + lane]      = k1 * c - k2 * s;
    g_kp[drow + lane + 32] = k2 * c + k1 * s;
    g_vp[drow + lane]      = src[2048 + h * 64 + lane];
    g_vp[drow + lane + 32] = src[2048 + h * 64 + lane + 32];
    if (lane == 0) {
        g_qstart[bh * Ss + slot] = startn;
        g_orig  [bh * Ss + slot] = tok;
    }
}

// ---------------- attention: maxless partitioned flash, 256 q/block ----------
#define ATTN_SMEM ((4096 + 4096) * 4)
__global__ __launch_bounds__(256)
void attn_k() {
    int bh = blockIdx.y;
    int h = bh & 15;
    int q0 = blockIdx.x * 256;
    int tid = threadIdx.x;
    int j = q0 + tid;
    size_t base = (size_t)bh * Ss;
    extern __shared__ float sm[];
    float* Ks = sm;
    float* Vs = sm + 4096;

    float qreg[64];
    const float4* qp = (const float4*)(g_qp + (base + j) * HDim);
    #pragma unroll
    for (int d4 = 0; d4 < 16; d4++) {
        float4 v = qp[d4];
        qreg[d4*4+0] = v.x; qreg[d4*4+1] = v.y; qreg[d4*4+2] = v.z; qreg[d4*4+3] = v.w;
    }
    int startq = g_qstart[base + j];
    int orig   = g_orig[base + j];
    int kt0 = g_qstart[base + q0] >> 6;
    int ktE = (q0 >> 6) + 4;

    float l = 0.f;
    float acc[64];
    #pragma unroll
    for (int d = 0; d < 64; d++) acc[d] = 0.f;

    for (int kt = kt0; kt < ktE; ++kt) {
        int kb = kt * 64;
        __syncthreads();
        for (int e = tid; e < 1024; e += 256) {
            int r = e >> 4, c = (e & 15) * 4;
            size_t srow = (base + kb + r) * HDim;
            *(float4*)&Ks[r * 64 + c] = *(const float4*)(g_kp + srow + c);
            *(float4*)&Vs[r * 64 + c] = *(const float4*)(g_vp + srow + c);
        }
        __syncthreads();

        int kk0 = startq - kb; kk0 = kk0 > 0 ? kk0 : 0;
        int kk1 = j - kb + 1;  kk1 = kk1 < 64 ? kk1 : 64;

        #pragma unroll 1
        for (int kk = kk0; kk < kk1; ++kk) {
            float s0 = 0.f, s1 = 0.f, s2 = 0.f, s3 = 0.f;
            const float4* kr = (const float4*)&Ks[kk * 64];
            #pragma unroll
            for (int d4 = 0; d4 < 16; d4++) {
                float4 kv = kr[d4];
                s0 = fmaf(qreg[d4*4+0], kv.x, s0);
                s1 = fmaf(qreg[d4*4+1], kv.y, s1);
                s2 = fmaf(qreg[d4*4+2], kv.z, s2);
                s3 = fmaf(qreg[d4*4+3], kv.w, s3);
            }
            float p = fexp(((s0 + s1) + (s2 + s3)) * 0.125f);
            l += p;
            const float4* vr = (const float4*)&Vs[kk * 64];
            #pragma unroll
            for (int d4 = 0; d4 < 16; d4++) {
                float4 vv = vr[d4];
                acc[d4*4+0] = fmaf(p, vv.x, acc[d4*4+0]);
                acc[d4*4+1] = fmaf(p, vv.y, acc[d4*4+1]);
                acc[d4*4+2] = fmaf(p, vv.z, acc[d4*4+2]);
                acc[d4*4+3] = fmaf(p, vv.w, acc[d4*4+3]);
            }
        }
    }
    float inv = 1.f / l;
    __nv_bfloat162* oh = (__nv_bfloat162*)(g_cxh + (size_t)orig * Dm + h * HDim);
    __nv_bfloat162* ol = (__nv_bfloat162*)(g_cxl + (size_t)orig * Dm + h * HDim);
    #pragma unroll
    for (int d2 = 0; d2 < 32; d2++) {
        float v0 = acc[d2*2] * inv, v1 = acc[d2*2+1] * inv;
        __nv_bfloat16 h0 = __float2bfloat16(v0), h1 = __float2bfloat16(v1);
        __nv_bfloat162 H; H.x = h0; H.y = h1;
        oh[d2] = H;
        __nv_bfloat162 L;
        L.x = __float2bfloat16(v0 - __bfloat162float(h0));
        L.y = __float2bfloat16(v1 - __bfloat162float(h1));
        ol[d2] = L;
    }
}

// ---------------- host launcher ----------------------------------------------
#define SYM(p, s) do { void* _t; cudaGetSymbolAddress(&_t, s); p = (decltype(p))_t; } while (0)

extern "C" void kernel_launch(void* const* d_in, const int* in_sizes, int n_in,
                              void* d_out, int out_size) {
    const float* x      = (const float*)d_in[0];
    const float* attn_w = (const float*)d_in[1];
    const float* ffn_w  = (const float*)d_in[2];
    const float* Wq     = (const float*)d_in[3];
    const float* Wk     = (const float*)d_in[4];
    const float* Wv     = (const float*)d_in[5];
    const float* Wo     = (const float*)d_in[6];
    const float* Wr     = (const float*)d_in[7];
    const float* w1     = (const float*)d_in[8];
    const float* w2     = (const float*)d_in[9];
    const float* w3     = (const float*)d_in[10];
    float* out = (float*)d_out;

    float *p_qkvr, *p_x2;
    SYM(p_qkvr, g_qkvr); SYM(p_x2, g_x2);
    __nv_bfloat16 *p_hh, *p_hl, *p_cxh, *p_cxl, *p_s1h, *p_s1l;
    SYM(p_hh, g_hh); SYM(p_hl, g_hl); SYM(p_cxh, g_cxh); SYM(p_cxl, g_cxl);
    SYM(p_s1h, g_s1h); SYM(p_s1l, g_s1l);
    __nv_bfloat16 *wAh, *wAl, *woh, *wol, *w12h, *w12l, *w3h, *w3l;
    SYM(wAh, g_wAh); SYM(wAl, g_wAl); SYM(woh, g_woh); SYM(wol, g_wol);
    SYM(w12h, g_w12h); SYM(w12l, g_w12l); SYM(w3h, g_w3h); SYM(w3l, g_w3l);

    cudaFuncSetAttribute(attn_k, cudaFuncAttributeMaxDynamicSharedMemorySize, ATTN_SMEM);
    cudaFuncSetAttribute(gemm_hmma, cudaFuncAttributeMaxDynamicSharedMemorySize, GH_SMEM);

    // single consolidated weight-prep launch
    wsplit_all<<<16512, dim3(32, 8)>>>(Wq, Wk, Wv, Wo, Wr, w1, w2, w3,
                                       wAh, wAl, woh, wol, w12h, w12l, w3h, w3l);

    // h = rmsnorm(x) -> bf16 split
    rmsnorm_k<<<TOK, 256>>>(x, attn_w, p_hh, p_hl);

    // fused q|k|v|router GEMM
    gemm_hmma<<<dim3(NQKV/128, TOK/128), 256, GH_SMEM>>>(
        p_hh, p_hl, wAh, wAl, nullptr, p_qkvr, TOK, NQKV, NQKV, Dm,
        nullptr, nullptr, 0);

    // node/pos + partition & rope ; attention
    node_pos_k<<<32, 256>>>();
    permute_k<<<TOK * Hh / 8, 256>>>();
    attn_k<<<dim3(Ss / 256, 2 * Hh), 256, ATTN_SMEM>>>();

    // x2 = x + ctx @ Wo
    gemm_hmma<<<dim3(Dm/128, TOK/128), 256, GH_SMEM>>>(
        p_cxh, p_cxl, woh, wol, x, p_x2, TOK, Dm, Dm, Dm, nullptr, nullptr, 0);

    // h2 = rmsnorm(x2)
    rmsnorm_k<<<TOK, 256>>>(p_x2, ffn_w, p_hh, p_hl);

    // fused w1|w2 GEMM with SwiGLU epilogue -> s1 (bf16 split)
    gemm_hmma<<<dim3(2*Ff/128, TOK/128), 256, GH_SMEM>>>(
        p_hh, p_hl, w12h, w12l, nullptr, nullptr, TOK, 2*Ff, 0, Dm,
        p_s1h, p_s1l, 1);

    // out = x2 + s1 @ w3
    gemm_hmma<<<dim3(Dm/128, TOK/128), 256, GH_SMEM>>>(
        p_s1h, p_s1l, w3h, w3l, p_x2, out, TOK, Dm, Dm, Ff, nullptr, nullptr, 0);
}

// round 15
// speedup vs baseline: 1.0714x; 1.0360x over previous
#include <cuda_runtime.h>
#include <cuda_bf16.h>
#include <math.h>
#include <math_constants.h>
#include <stdint.h>

#define TOK 4096   // B*S
#define Dm  1024
#define Hh  16
#define HDim 64
#define Ff  4096
#define Ss  2048
#define NQKV 3200  // q(1024) k(1024) v(1024) router(64) pad(64)

// ---------------- fp32 scratch ----------------------------------------------
__device__ float g_qkvr[TOK*NQKV];
__device__ float g_x2 [TOK*Dm];
__device__ int   g_node[TOK*Hh];
__device__ float g_pos [TOK*Hh];
__device__ int   g_start [32*4];
__device__ int   g_qstart[32*Ss];
__device__ int   g_orig  [32*Ss];
__device__ float g_qp[32*Ss*HDim];
__device__ float g_kp[32*Ss*HDim];
__device__ float g_vp[32*Ss*HDim];

// ---------------- bf16 split activations ------------------------------------
__device__ __nv_bfloat16 g_hh [TOK*Dm], g_hl [TOK*Dm];
__device__ __nv_bfloat16 g_cxh[TOK*Dm], g_cxl[TOK*Dm];
__device__ __nv_bfloat16 g_s1h[TOK*Ff], g_s1l[TOK*Ff];

// ---------------- bf16 split transposed weights [N,K] -----------------------
__device__ __nv_bfloat16 g_wAh[NQKV*Dm], g_wAl[NQKV*Dm];    // Wq|Wk|Wv|Wr|0
__device__ __nv_bfloat16 g_woh[Dm*Dm],   g_wol[Dm*Dm];
__device__ __nv_bfloat16 g_w12h[2*Ff*Dm], g_w12l[2*Ff*Dm];  // w1/w2 interleaved
__device__ __nv_bfloat16 g_w3h[Dm*Ff],   g_w3l[Dm*Ff];

// ---------------- helpers -----------------------------------------------------
__device__ __forceinline__ uint32_t s2u(const void* p) {
    uint32_t a;
    asm("{ .reg .u64 t; cvta.to.shared.u64 t, %1; cvt.u32.u64 %0, t; }" : "=r"(a) : "l"(p));
    return a;
}

#define LDSM4(r, addr) \
    asm volatile("ldmatrix.sync.aligned.m8n8.x4.shared.b16 {%0,%1,%2,%3}, [%4];" \
        : "=r"((r)[0]), "=r"((r)[1]), "=r"((r)[2]), "=r"((r)[3]) : "r"(addr))

#define MMA(d, a, b) \
    asm volatile("mma.sync.aligned.m16n8k16.row.col.f32.bf16.bf16.f32 " \
        "{%0,%1,%2,%3}, {%4,%5,%6,%7}, {%8,%9}, {%0,%1,%2,%3};" \
        : "+f"((d)[0]), "+f"((d)[1]), "+f"((d)[2]), "+f"((d)[3]) \
        : "r"((a)[0]), "r"((a)[1]), "r"((a)[2]), "r"((a)[3]), "r"((b)[0]), "r"((b)[1]))

#define CPASYNC(dst, src) \
    asm volatile("cp.async.cg.shared.global [%0], [%1], 16;" :: "r"(dst), "l"(src))

// ---------------- fast exp (FMA pipe only) ----------------------------------
__device__ __forceinline__ float fexp(float x) {
    x = fminf(fmaxf(x, -87.0f), 88.0f);
    float y = x * 1.4426950408889634f;
    float n = rintf(y);
    float f = y - n;
    float p = 1.3333558146e-3f;
    p = fmaf(p, f, 9.6181291076e-3f);
    p = fmaf(p, f, 5.5504108665e-2f);
    p = fmaf(p, f, 2.4022650696e-1f);
    p = fmaf(p, f, 6.9314718056e-1f);
    p = fmaf(p, f, 1.0f);
    return p * __int_as_float(((int)n + 127) << 23);
}

// ---------------- HMMA split-bf16 GEMM, 2-stage, 2 CTAs/SM -------------------
#define BUF_BYTES 40960
#define GH_SMEM   (2 * BUF_BYTES)

__global__ __launch_bounds__(256, 2)
void gemm_hmma(const __nv_bfloat16* __restrict__ Ah, const __nv_bfloat16* __restrict__ Al,
               const __nv_bfloat16* __restrict__ Bh, const __nv_bfloat16* __restrict__ Bl,
               const float* __restrict__ R, float* __restrict__ C,
               int M, int Nc, int ldc, int K,
               __nv_bfloat16* __restrict__ Oh, __nv_bfloat16* __restrict__ Ol, int swiglu) {
    extern __shared__ char smraw[];
    const int tid  = threadIdx.x;
    const int lane = tid & 31, wid = tid >> 5;
    const int m0 = blockIdx.y * 128, n0 = blockIdx.x * 128;
    const int warp_m = (wid >> 2) * 64, warp_n = (wid & 3) * 32;
    const int nc = K >> 5;
    const uint32_t sb = s2u(smraw);

    const char* gA  = (const char*)Ah + (size_t)m0 * K * 2;
    const char* gAl = (const char*)Al + (size_t)m0 * K * 2;
    const char* gB  = (const char*)Bh + (size_t)n0 * K * 2;
    const char* gBl = (const char*)Bl + (size_t)n0 * K * 2;

    int lr0 = tid >> 2,          lc0 = (tid & 3) * 16;
    int lr1 = (tid + 256) >> 2,  lc1 = lc0;

    #define ISSUE(buf, kc) do { \
        uint32_t db = sb + (buf) * BUF_BYTES; \
        size_t ko = (size_t)(kc) * 64; \
        uint32_t so0 = lr0 * 80 + lc0, so1 = lr1 * 80 + lc1; \
        size_t go0 = (size_t)lr0 * (K * 2) + ko + lc0; \
        size_t go1 = (size_t)lr1 * (K * 2) + ko + lc1; \
        CPASYNC(db + so0,         gA  + go0); CPASYNC(db + so1,         gA  + go1); \
        CPASYNC(db + 10240 + so0, gAl + go0); CPASYNC(db + 10240 + so1, gAl + go1); \
        CPASYNC(db + 20480 + so0, gB  + go0); CPASYNC(db + 20480 + so1, gB  + go1); \
        CPASYNC(db + 30720 + so0, gBl + go0); CPASYNC(db + 30720 + so1, gBl + go1); \
        asm volatile("cp.async.commit_group;"); \
    } while (0)

    ISSUE(0, 0);
    ISSUE(1, 1);

    float acc[4][4][4];
    #pragma unroll
    for (int i = 0; i < 4; i++)
        #pragma unroll
        for (int j = 0; j < 4; j++)
            #pragma unroll
            for (int q = 0; q < 4; q++) acc[i][j][q] = 0.f;

    const int a_row = (lane & 7) + ((lane >> 3) & 1) * 8;
    const int a_cb  = (lane >> 4) * 16;
    const int b_row = (lane & 7) + (lane >> 4) * 8;
    const int b_cb  = ((lane >> 3) & 1) * 16;
    const uint32_t aoff = (warp_m + a_row) * 80 + a_cb;
    const uint32_t boff = 20480 + (warp_n + b_row) * 80 + b_cb;

    #pragma unroll 1
    for (int kc = 0; kc < nc; kc++) {
        if (kc + 1 < nc) asm volatile("cp.async.wait_group 1;");
        else             asm volatile("cp.async.wait_group 0;");
        __syncthreads();
        uint32_t db = sb + (kc & 1) * BUF_BYTES;
        #pragma unroll
        for (int ks = 0; ks < 2; ks++) {
            uint32_t ah[4][4], bh[4][2], bl[4][2];
            #pragma unroll
            for (int mt = 0; mt < 4; mt++)
                LDSM4(ah[mt], db + aoff + mt * (16 * 80) + ks * 32);
            #pragma unroll
            for (int p = 0; p < 2; p++) {
                uint32_t bd = db + boff + p * (16 * 80) + ks * 32;
                LDSM4(&bh[2 * p][0], bd);
                LDSM4(&bl[2 * p][0], bd + 10240);
            }
            #pragma unroll
            for (int mt = 0; mt < 4; mt++)
                #pragma unroll
                for (int nt = 0; nt < 4; nt++) MMA(acc[mt][nt], ah[mt], bh[nt]);
            #pragma unroll
            for (int mt = 0; mt < 4; mt++)
                #pragma unroll
                for (int nt = 0; nt < 4; nt++) MMA(acc[mt][nt], ah[mt], bl[nt]);
            uint32_t al[4][4];
            #pragma unroll
            for (int mt = 0; mt < 4; mt++)
                LDSM4(al[mt], db + aoff + mt * (16 * 80) + ks * 32 + 10240);
            #pragma unroll
            for (int mt = 0; mt < 4; mt++)
                #pragma unroll
                for (int nt = 0; nt < 4; nt++) MMA(acc[mt][nt], al[mt], bh[nt]);
        }
        __syncthreads();
        if (kc + 2 < nc) ISSUE(kc & 1, kc + 2);
    }
    #undef ISSUE

    const int g  = lane >> 2;
    const int cc = (lane & 3) * 2;

    if (swiglu) {
        float* sm2 = (float*)smraw;          // [128][68] fp32 staging for a2
        if ((wid & 3) >= 2) {
            #pragma unroll
            for (int mt = 0; mt < 4; mt++) {
                int row0 = warp_m + mt * 16 + g;
                #pragma unroll
                for (int nt = 0; nt < 4; nt++) {
                    int c = warp_n - 64 + nt * 8 + cc;
                    sm2[row0 * 68 + c]           = acc[mt][nt][0];
                    sm2[row0 * 68 + c + 1]       = acc[mt][nt][1];
                    sm2[(row0 + 8) * 68 + c]     = acc[mt][nt][2];
                    sm2[(row0 + 8) * 68 + c + 1] = acc[mt][nt][3];
                }
            }
        }
        __syncthreads();
        if ((wid & 3) < 2) {
            size_t colbase = (size_t)blockIdx.x * 64;
            #pragma unroll
            for (int mt = 0; mt < 4; mt++) {
                #pragma unroll
                for (int rr = 0; rr < 2; rr++) {
                    int row = warp_m + mt * 16 + g + rr * 8;
                    size_t orow = (size_t)(m0 + row) * Ff + colbase;
                    #pragma unroll
                    for (int nt = 0; nt < 4; nt++) {
                        int c = warp_n + nt * 8 + cc;
                        float a1a = acc[mt][nt][rr * 2], a1b = acc[mt][nt][rr * 2 + 1];
                        float a2a = sm2[row * 68 + c], a2b = sm2[row * 68 + c + 1];
                        float r0 = a1a / (1.f + fexp(-a1a)) * a2a;
                        float r1 = a1b / (1.f + fexp(-a1b)) * a2b;
                        __nv_bfloat16 h0 = __float2bfloat16(r0), h1 = __float2bfloat16(r1);
                        __nv_bfloat162 H; H.x = h0; H.y = h1;
                        *(__nv_bfloat162*)(Oh + orow + c) = H;
                        __nv_bfloat162 L;
                        L.x = __float2bfloat16(r0 - __bfloat162float(h0));
                        L.y = __float2bfloat16(r1 - __bfloat162float(h1));
                        *(__nv_bfloat162*)(Ol + orow + c) = L;
                    }
                }
            }
        }
        return;
    }

    #pragma unroll
    for (int mt = 0; mt < 4; mt++) {
        int row0 = m0 + warp_m + mt * 16 + g;
        #pragma unroll
        for (int nt = 0; nt < 4; nt++) {
            int col = n0 + warp_n + nt * 8 + cc;
            if (col < Nc) {
                float2 v0 = make_float2(acc[mt][nt][0], acc[mt][nt][1]);
                float2 v1 = make_float2(acc[mt][nt][2], acc[mt][nt][3]);
                if (R) {
                    float2 r0 = *(const float2*)(R + (size_t)row0 * ldc + col);
                    float2 r1 = *(const float2*)(R + (size_t)(row0 + 8) * ldc + col);
                    v0.x += r0.x; v0.y += r0.y; v1.x += r1.x; v1.y += r1.y;
                }
                *(float2*)(C + (size_t)row0 * ldc + col)       = v0;
                *(float2*)(C + (size_t)(row0 + 8) * ldc + col) = v1;
            }
        }
    }
}

// ---------------- consolidated weight transpose + bf16 split -----------------
__global__ void wsplit_all(const float* __restrict__ Wq, const float* __restrict__ Wk,
                           const float* __restrict__ Wv, const float* __restrict__ Wo,
                           const float* __restrict__ Wr, const float* __restrict__ w1,
                           const float* __restrict__ w2, const float* __restrict__ w3,
                           __nv_bfloat16* __restrict__ wAh, __nv_bfloat16* __restrict__ wAl,
                           __nv_bfloat16* __restrict__ woh, __nv_bfloat16* __restrict__ wol,
                           __nv_bfloat16* __restrict__ w12h, __nv_bfloat16* __restrict__ w12l,
                           __nv_bfloat16* __restrict__ w3h, __nv_bfloat16* __restrict__ w3l) {
    int idx = blockIdx.x;
    const float* W;
    __nv_bfloat16 *Th, *Tl;
    int Kd, Nd, mode, Nvalid, bx, by;
    if (idx < 4096) {
        int which = idx >> 10, local = idx & 1023;
        bx = local & 31; by = local >> 5;
        Kd = Dm; Nd = Dm; mode = 0; Nvalid = Dm;
        if      (which == 0) { W = Wq; Th = wAh;             Tl = wAl; }
        else if (which == 1) { W = Wk; Th = wAh + 1024*Dm;   Tl = wAl + 1024*Dm; }
        else if (which == 2) { W = Wv; Th = wAh + 2048*Dm;   Tl = wAl + 2048*Dm; }
        else                 { W = Wo; Th = woh;             Tl = wol; }
    } else if (idx < 4224) {
        int local = idx - 4096;
        bx = local & 3; by = local >> 2;
        W = Wr; Th = wAh + (size_t)3072*Dm; Tl = wAl + (size_t)3072*Dm;
        Kd = Dm; Nd = 64; mode = 0; Nvalid = 64;
    } else if (idx < 8320) {
        int local = idx - 4224;
        bx = local & 127; by = local >> 7;
        W = w1; Th = w12h; Tl = w12l; Kd = Dm; Nd = Ff; mode = 1; Nvalid = Ff;
    } else if (idx < 12416) {
        int local = idx - 8320;
        bx = local & 127; by = local >> 7;
        W = w2; Th = w12h; Tl = w12l; Kd = Dm; Nd = Ff; mode = 2; Nvalid = Ff;
    } else {
        int local = idx - 12416;
        bx = local & 31; by = local >> 5;
        W = w3; Th = w3h; Tl = w3l; Kd = Ff; Nd = Dm; mode = 0; Nvalid = Dm;
    }

    __shared__ float t[32][33];
    int n0 = bx * 32, k0 = by * 32;
    int tx = threadIdx.x, ty = threadIdx.y;
    #pragma unroll
    for (int i = 0; i < 4; i++)
        t[ty + i * 8][tx] = (n0 + tx < Nvalid)
            ? W[(size_t)(k0 + ty + i * 8) * Nd + n0 + tx] : 0.f;
    __syncthreads();
    #pragma unroll
    for (int i = 0; i < 4; i++) {
        int r = ty + i * 8;
        int n = n0 + r;
        size_t orow = (mode == 0) ? (size_t)n
                    : (size_t)((n >> 6) * 128 + (n & 63) + ((mode == 2) ? 64 : 0));
        float v = t[tx][r];
        __nv_bfloat16 hb = __float2bfloat16(v);
        size_t o = orow * Kd + k0 + tx;
        Th[o] = hb;
        Tl[o] = __float2bfloat16(v - __bfloat162float(hb));
    }
}

// ---------------- rmsnorm -> bf16 split --------------------------------------
__global__ void rmsnorm_k(const float* __restrict__ x, const float* __restrict__ w,
                          __nv_bfloat16* __restrict__ oh, __nv_bfloat16* __restrict__ ol) {
    int row = blockIdx.x;
    const float4* xr = (const float4*)(x + (size_t)row * Dm);
    float4 v = xr[threadIdx.x];
    float ss = v.x*v.x + v.y*v.y + v.z*v.z + v.w*v.w;
    #pragma unroll
    for (int o = 16; o; o >>= 1) ss += __shfl_xor_sync(0xffffffffu, ss, o);
    __shared__ float sws[8];
    int lane = threadIdx.x & 31, wid = threadIdx.x >> 5;
    if (lane == 0) sws[wid] = ss;
    __syncthreads();
    if (threadIdx.x == 0) {
        float t = 0.f;
        #pragma unroll
        for (int i = 0; i < 8; i++) t += sws[i];
        sws[0] = rsqrtf(t * (1.0f / Dm) + 1e-6f);
    }
    __syncthreads();
    float inv = sws[0];
    float4 wv = ((const float4*)w)[threadIdx.x];
    float4 o4;
    o4.x = v.x * inv * wv.x; o4.y = v.y * inv * wv.y;
    o4.z = v.z * inv * wv.z; o4.w = v.w * inv * wv.w;
    __nv_bfloat16 h0 = __float2bfloat16(o4.x), h1 = __float2bfloat16(o4.y);
    __nv_bfloat16 h2 = __float2bfloat16(o4.z), h3 = __float2bfloat16(o4.w);
    __nv_bfloat162 H0; H0.x = h0; H0.y = h1;
    __nv_bfloat162 H1; H1.x = h2; H1.y = h3;
    __nv_bfloat162* ph = (__nv_bfloat162*)(oh + (size_t)row * Dm);
    ph[threadIdx.x * 2]     = H0;
    ph[threadIdx.x * 2 + 1] = H1;
    __nv_bfloat162 L0, L1;
    L0.x = __float2bfloat16(o4.x - __bfloat162float(h0));
    L0.y = __float2bfloat16(o4.y - __bfloat162float(h1));
    L1.x = __float2bfloat16(o4.z - __bfloat162float(h2));
    L1.y = __float2bfloat16(o4.w - __bfloat162float(h3));
    __nv_bfloat162* pl = (__nv_bfloat162*)(ol + (size_t)row * Dm);
    pl[threadIdx.x * 2]     = L0;
    pl[threadIdx.x * 2 + 1] = L1;
}

// ---------------- node/pos + partition starts (parallel scan) ----------------
__global__ void node_pos_k() {
    int bh = blockIdx.x;
    int b = bh >> 4, h = bh & 15;
    int t = threadIdx.x;
    int lane = t & 31, wid = t >> 5;
    __shared__ int cnts[256][4];
    __shared__ int base[256][4];
    __shared__ int tot[4];
    int myn[8], posl[8];
    int local[4] = {0, 0, 0, 0};
    #pragma unroll
    for (int j = 0; j < 8; j++) {
        int s = t * 8 + j;
        int tok = b * Ss + s;
        const float* lp = g_qkvr + (size_t)tok * NQKV + 3072 + h * 4;
        float l0 = lp[0], l1 = lp[1], l2 = lp[2], l3 = lp[3];
        int n = 0; float bv = l0;
        if (l1 > bv) { bv = l1; n = 1; }
        if (l2 > bv) { bv = l2; n = 2; }
        if (l3 > bv) { bv = l3; n = 3; }
        myn[j] = n;
        posl[j] = local[n];
        local[n]++;
    }
    cnts[t][0] = local[0]; cnts[t][1] = local[1];
    cnts[t][2] = local[2]; cnts[t][3] = local[3];
    __syncthreads();
    if (wid < 4) {
        int v = wid;
        int vals[8], part = 0;
        #pragma unroll
        for (int m = 0; m < 8; m++) { vals[m] = cnts[lane * 8 + m][v]; part += vals[m]; }
        int scan = part;
        #pragma unroll
        for (int o = 1; o < 32; o <<= 1) {
            int u = __shfl_up_sync(0xffffffffu, scan, o);
            if (lane >= o) scan += u;
        }
        int excl = scan - part;
        int run = 0;
        #pragma unroll
        for (int m = 0; m < 8; m++) { base[lane * 8 + m][v] = excl + run; run += vals[m]; }
        if (lane == 31) tot[v] = excl + part;
    }
    __syncthreads();
    if (t == 0) {
        int st = 0;
        #pragma unroll
        for (int v = 0; v < 4; v++) { g_start[bh * 4 + v] = st; st += tot[v]; }
    }
    __syncthreads();
    #pragma unroll
    for (int j = 0; j < 8; j++) {
        int s = t * 8 + j;
        int tok = b * Ss + s;
        int n = myn[j];
        g_node[tok * Hh + h] = n;
        g_pos[tok * Hh + h] = (float)(base[t][n] + posl[j]);
    }
}

// ---------------- permute (node partition) + RoPE ----------------------------
__global__ void permute_k() {
    int inst = blockIdx.x * 8 + (threadIdx.x >> 5);   // tok*16 + h
    int lane = threadIdx.x & 31;
    int tok = inst >> 4, h = inst & 15;
    int b = tok >> 11;
    int bh = b * 16 + h;
    int n = g_node[tok * Hh + h];
    float pos = g_pos[tok * Hh + h];
    int startn = g_start[bh * 4 + n];
    int slot = startn + (int)pos;
    const float* src = g_qkvr + (size_t)tok * NQKV;
    float invf = exp2f(-(float)lane * (13.287712379549449f / 32.0f));
    float ang = pos * invf;
    float s, c;
    sincosf(ang, &s, &c);
    size_t drow = ((size_t)bh * Ss + slot) * HDim;
    float q1 = src[h * 64 + lane], q2 = src[h * 64 + lane + 32];
    g_qp[drow + lane]      = q1 * c - q2 * s;
    g_qp[drow + lane + 32] = q2 * c + q1 * s;
    float k1 = src[1024 + h * 64 + lane], k2 = src[1024 + h * 64 + lane + 32];
    g_kp[drow + lane]      = k1 * c - k2 * s;
    g_kp[drow + lane + 32] = k2 * c + k1 * s;
    g_vp[drow + lane]      = src[2048 + h * 64 + lane];
    g_vp[drow + lane + 32] = src[2048 + h * 64 + lane + 32];
    if (lane == 0) {
        g_qstart[bh * Ss + slot] = startn;
        g_orig  [bh * Ss + slot] = tok;
    }
}

// ---------------- attention: maxless single-pass partitioned flash -----------
#define ATTN_SMEM ((4096 + 4096) * 4)
__global__ __launch_bounds__(128)
void attn_k() {
    int bh = blockIdx.y;
    int h = bh & 15;
    int q0 = blockIdx.x * 128;
    int tid = threadIdx.x;
    int j = q0 + tid;
    size_t base = (size_t)bh * Ss;
    extern __shared__ float sm[];
    float* Ks = sm;
    float* Vs = sm + 4096;

    float qreg[64];
    const float4* qp = (const float4*)(g_qp + (base + j) * HDim);
    #pragma unroll
    for (int d4 = 0; d4 < 16; d4++) {
        float4 v = qp[d4];
        qreg[d4*4+0] = v.x; qreg[d4*4+1] = v.y; qreg[d4*4+2] = v.z; qreg[d4*4+3] = v.w;
    }
    int startq = g_qstart[base + j];
    int orig   = g_orig[base + j];
    int kt0 = g_qstart[base + q0] >> 6;
    int ktE = (q0 >> 6) + 2;

    float l = 0.f;
    float acc[64];
    #pragma unroll
    for (int d = 0; d < 64; d++) acc[d] = 0.f;

    for (int kt = kt0; kt < ktE; ++kt) {
        int kb = kt * 64;
        __syncthreads();
        for (int e = tid; e < 1024; e += 128) {
            int r = e >> 4, c = (e & 15) * 4;
            size_t srow = (base + kb + r) * HDim;
            *(float4*)&Ks[r * 64 + c] = *(const float4*)(g_kp + srow + c);
            *(float4*)&Vs[r * 64 + c] = *(const float4*)(g_vp + srow + c);
        }
        __syncthreads();

        int kk0 = startq - kb; kk0 = kk0 > 0 ? kk0 : 0;
        int kk1 = j - kb + 1;  kk1 = kk1 < 64 ? kk1 : 64;

        #pragma unroll 1
        for (int kk = kk0; kk < kk1; ++kk) {
            float s0 = 0.f, s1 = 0.f, s2 = 0.f, s3 = 0.f;
            const float4* kr = (const float4*)&Ks[kk * 64];
            #pragma unroll
            for (int d4 = 0; d4 < 16; d4++) {
                float4 kv = kr[d4];
                s0 = fmaf(qreg[d4*4+0], kv.x, s0);
                s1 = fmaf(qreg[d4*4+1], kv.y, s1);
                s2 = fmaf(qreg[d4*4+2], kv.z, s2);
                s3 = fmaf(qreg[d4*4+3], kv.w, s3);
            }
            float p = fexp(((s0 + s1) + (s2 + s3)) * 0.125f);
            l += p;
            const float4* vr = (const float4*)&Vs[kk * 64];
            #pragma unroll
            for (int d4 = 0; d4 < 16; d4++) {
                float4 vv = vr[d4];
                acc[d4*4+0] = fmaf(p, vv.x, acc[d4*4+0]);
                acc[d4*4+1] = fmaf(p, vv.y, acc[d4*4+1]);
                acc[d4*4+2] = fmaf(p, vv.z, acc[d4*4+2]);
                acc[d4*4+3] = fmaf(p, vv.w, acc[d4*4+3]);
            }
        }
    }
    float inv = 1.f / l;
    __nv_bfloat162* oh = (__nv_bfloat162*)(g_cxh + (size_t)orig * Dm + h * HDim);
    __nv_bfloat162* ol = (__nv_bfloat162*)(g_cxl + (size_t)orig * Dm + h * HDim);
    #pragma unroll
    for (int d2 = 0; d2 < 32; d2++) {
        float v0 = acc[d2*2] * inv, v1 = acc[d2*2+1] * inv;
        __nv_bfloat16 h0 = __float2bfloat16(v0), h1 = __float2bfloat16(v1);
        __nv_bfloat162 H; H.x = h0; H.y = h1;
        oh[d2] = H;
        __nv_bfloat162 L;
        L.x = __float2bfloat16(v0 - __bfloat162float(h0));
        L.y = __float2bfloat16(v1 - __bfloat162float(h1));
        ol[d2] = L;
    }
}

// ---------------- host launcher ----------------------------------------------
#define SYM(p, s) do { void* _t; cudaGetSymbolAddress(&_t, s); p = (decltype(p))_t; } while (0)

extern "C" void kernel_launch(void* const* d_in, const int* in_sizes, int n_in,
                              void* d_out, int out_size) {
    const float* x      = (const float*)d_in[0];
    const float* attn_w = (const float*)d_in[1];
    const float* ffn_w  = (const float*)d_in[2];
    const float* Wq     = (const float*)d_in[3];
    const float* Wk     = (const float*)d_in[4];
    const float* Wv     = (const float*)d_in[5];
    const float* Wo     = (const float*)d_in[6];
    const float* Wr     = (const float*)d_in[7];
    const float* w1     = (const float*)d_in[8];
    const float* w2     = (const float*)d_in[9];
    const float* w3     = (const float*)d_in[10];
    float* out = (float*)d_out;

    float *p_qkvr, *p_x2;
    SYM(p_qkvr, g_qkvr); SYM(p_x2, g_x2);
    __nv_bfloat16 *p_hh, *p_hl, *p_cxh, *p_cxl, *p_s1h, *p_s1l;
    SYM(p_hh, g_hh); SYM(p_hl, g_hl); SYM(p_cxh, g_cxh); SYM(p_cxl, g_cxl);
    SYM(p_s1h, g_s1h); SYM(p_s1l, g_s1l);
    __nv_bfloat16 *wAh, *wAl, *woh, *wol, *w12h, *w12l, *w3h, *w3l;
    SYM(wAh, g_wAh); SYM(wAl, g_wAl); SYM(woh, g_woh); SYM(wol, g_wol);
    SYM(w12h, g_w12h); SYM(w12l, g_w12l); SYM(w3h, g_w3h); SYM(w3l, g_w3l);

    cudaFuncSetAttribute(attn_k, cudaFuncAttributeMaxDynamicSharedMemorySize, ATTN_SMEM);
    cudaFuncSetAttribute(gemm_hmma, cudaFuncAttributeMaxDynamicSharedMemorySize, GH_SMEM);

    // single consolidated weight-prep launch
    wsplit_all<<<16512, dim3(32, 8)>>>(Wq, Wk, Wv, Wo, Wr, w1, w2, w3,
                                       wAh, wAl, woh, wol, w12h, w12l, w3h, w3l);

    // h = rmsnorm(x) -> bf16 split
    rmsnorm_k<<<TOK, 256>>>(x, attn_w, p_hh, p_hl);

    // fused q|k|v|router GEMM (Nc=3136: pad columns never written)
    gemm_hmma<<<dim3(NQKV/128, TOK/128), 256, GH_SMEM>>>(
        p_hh, p_hl, wAh, wAl, nullptr, p_qkvr, TOK, 3136, NQKV, Dm,
        nullptr, nullptr, 0);

    // node/pos + partition & rope ; attention
    node_pos_k<<<32, 256>>>();
    permute_k<<<TOK * Hh / 8, 256>>>();
    attn_k<<<dim3(Ss / 128, 2 * Hh), 128, ATTN_SMEM>>>();

    // x2 = x + ctx @ Wo
    gemm_hmma<<<dim3(Dm/128, TOK/128), 256, GH_SMEM>>>(
        p_cxh, p_cxl, woh, wol, x, p_x2, TOK, Dm, Dm, Dm, nullptr, nullptr, 0);

    // h2 = rmsnorm(x2)
    rmsnorm_k<<<TOK, 256>>>(p_x2, ffn_w, p_hh, p_hl);

    // fused w1|w2 GEMM with SwiGLU epilogue -> s1 (bf16 split)
    gemm_hmma<<<dim3(2*Ff/128, TOK/128), 256, GH_SMEM>>>(
        p_hh, p_hl, w12h, w12l, nullptr, nullptr, TOK, 2*Ff, 0, Dm,
        p_s1h, p_s1l, 1);

    // out = x2 + s1 @ w3
    gemm_hmma<<<dim3(Dm/128, TOK/128), 256, GH_SMEM>>>(
        p_s1h, p_s1l, w3h, w3l, p_x2, out, TOK, Dm, Dm, Ff, nullptr, nullptr, 0);
}